// round 16
// baseline (speedup 1.0000x reference)
#include <cuda_runtime.h>
#include <cuda_bf16.h>
#include <math.h>

#define Bc 4
#define Cc 128
#define Lc 4096
#define Hh 4

typedef __nv_bfloat16 bf16;

// qscale = hd^-1/2 * log2(e), folded into W_q rows
#define QSCALE (0.17677669529663687f * 1.4426950408889634f)

// Scratch (allocation-free __device__ globals, 16B-aligned)
__device__ __align__(16) bf16 g_qkvb[Bc * 3 * Cc * Lc];  // qkv bf16      (12.6 MB)
__device__ __align__(16) bf16 g_oattb[Bc * Cc * Lc];     // attn out      (4 MB)
__device__ __align__(16) bf16 g_wqb[3 * Cc * Cc];
__device__ __align__(16) bf16 g_wpb[Cc * Cc];
__device__ __align__(16) float g_gnscl[Bc * Cc];         // per (b,c) scale
__device__ __align__(16) float g_gnshf[Bc * Cc];         // per (b,c) shift

// ---------------------------------------------------------------------------
// helpers
// ---------------------------------------------------------------------------
__device__ __forceinline__ void ldsm_x4_t(unsigned& r0, unsigned& r1, unsigned& r2, unsigned& r3, const void* p) {
    unsigned addr = (unsigned)__cvta_generic_to_shared(p);
    asm volatile("ldmatrix.sync.aligned.m8n8.x4.trans.shared.b16 {%0,%1,%2,%3}, [%4];"
                 : "=r"(r0), "=r"(r1), "=r"(r2), "=r"(r3) : "r"(addr));
}
__device__ __forceinline__ void ldsm_x4(unsigned& r0, unsigned& r1, unsigned& r2, unsigned& r3, const void* p) {
    unsigned addr = (unsigned)__cvta_generic_to_shared(p);
    asm volatile("ldmatrix.sync.aligned.m8n8.x4.shared.b16 {%0,%1,%2,%3}, [%4];"
                 : "=r"(r0), "=r"(r1), "=r"(r2), "=r"(r3) : "r"(addr));
}
__device__ __forceinline__ void mma16816(float* d, const unsigned* a, unsigned b0, unsigned b1) {
    asm volatile(
        "mma.sync.aligned.m16n8k16.row.col.f32.bf16.bf16.f32 "
        "{%0,%1,%2,%3},{%4,%5,%6,%7},{%8,%9},{%0,%1,%2,%3};"
        : "+f"(d[0]), "+f"(d[1]), "+f"(d[2]), "+f"(d[3])
        : "r"(a[0]), "r"(a[1]), "r"(a[2]), "r"(a[3]), "r"(b0), "r"(b1));
}
__device__ __forceinline__ unsigned pack_bf16(float lo, float hi) {
    __nv_bfloat162 h = __float22bfloat162_rn(make_float2(lo, hi));
    return *reinterpret_cast<unsigned*>(&h);
}
// {hi, lo} fp32 -> bf16x2 (lo in low half)
__device__ __forceinline__ unsigned cvtb2(float hi, float lo) {
    unsigned r;
    asm("cvt.rn.bf16x2.f32 %0, %1, %2;" : "=r"(r) : "f"(hi), "f"(lo));
    return r;
}
// packed bf16x2 2^x
__device__ __forceinline__ unsigned ex2b2(unsigned x) {
    unsigned r;
    asm("ex2.approx.ftz.bf16x2 %0, %1;" : "=r"(r) : "r"(x));
    return r;
}
__device__ __forceinline__ void cp16(void* smem, const void* gmem) {
    unsigned s = (unsigned)__cvta_generic_to_shared(smem);
    asm volatile("cp.async.cg.shared.global [%0], [%1], 16;" :: "r"(s), "l"(gmem));
}
#define CP_COMMIT() asm volatile("cp.async.commit_group;")
#define CP_WAIT(N)  asm volatile("cp.async.wait_group %0;" :: "n"(N))

// ---------------------------------------------------------------------------
// Weight prep: fp32 -> bf16, qscale folded into Q rows of w_qkv
// ---------------------------------------------------------------------------
__global__ __launch_bounds__(256) void prep_w_kernel(
    const float* __restrict__ wq, const float* __restrict__ wp,
    bf16* __restrict__ wqb, bf16* __restrict__ wpb)
{
    int i = blockIdx.x * 256 + threadIdx.x;
    int NTH = gridDim.x * 256;
    for (int e = i; e < 3 * Cc * Cc; e += NTH) {
        int row = e >> 7;
        float s = ((row % 96) < 32) ? QSCALE : 1.f;
        wqb[e] = __float2bfloat16_rn(wq[e] * s);
    }
    for (int e = i; e < Cc * Cc; e += NTH)
        wpb[e] = __float2bfloat16_rn(wp[e]);
}

// ---------------------------------------------------------------------------
// GroupNorm stats: one block per (b, group); emits per-channel scale/shift.
// ---------------------------------------------------------------------------
__global__ __launch_bounds__(256) void gn_stats_kernel(
    const float* __restrict__ x,
    const float* __restrict__ gamma,
    const float* __restrict__ beta,
    float* __restrict__ gnscl,
    float* __restrict__ gnshf)
{
    const int GS = 4 * Lc;  // 16384
    int bg = blockIdx.x;    // b*32 + g
    size_t base = (size_t)bg * GS;

    float s = 0.f, s2 = 0.f;
    for (int i = threadIdx.x; i < GS; i += 256) {
        float v = x[base + i];
        s += v;
        s2 += v * v;
    }
    __shared__ float rs[256], rs2[256];
    rs[threadIdx.x] = s;
    rs2[threadIdx.x] = s2;
    __syncthreads();
    for (int st = 128; st > 0; st >>= 1) {
        if (threadIdx.x < st) {
            rs[threadIdx.x] += rs[threadIdx.x + st];
            rs2[threadIdx.x] += rs2[threadIdx.x + st];
        }
        __syncthreads();
    }
    if (threadIdx.x < 4) {
        float mu = rs[0] * (1.f / GS);
        float var = rs2[0] * (1.f / GS) - mu * mu;
        float rinv = rsqrtf(var + 1e-5f);
        int b = bg >> 5;
        int c = (bg & 31) * 4 + threadIdx.x;
        float scl = rinv * gamma[c];
        gnscl[b * Cc + c] = scl;
        gnshf[b * Cc + c] = beta[c] - mu * scl;
    }
}

// ---------------------------------------------------------------------------
// bf16 MMA GEMM: Out[b][o][l] = sum_c W[o][c] * A[b][c][l]
// If xin != null: fused GroupNorm on the A-load path.
// ---------------------------------------------------------------------------
__global__ __launch_bounds__(256) void gemm_mma_kernel(
    const bf16* __restrict__ W,
    const bf16* __restrict__ A,
    const float* __restrict__ xin,
    const float* __restrict__ gnscl,
    const float* __restrict__ gnshf,
    bf16* __restrict__ outb,
    float* __restrict__ outf,
    const float* __restrict__ bias,
    const float* __restrict__ resid,
    int M)
{
    __shared__ __align__(16) bf16 sW[64][136];
    __shared__ __align__(16) bf16 sA[128][72];

    int b = blockIdx.z;
    int o0 = blockIdx.y * 64;
    int l0 = blockIdx.x * 64;
    int tid = threadIdx.x;
    int lane = tid & 31;
    int warp = tid >> 5;

    for (int i = tid; i < 64 * 16; i += 256) {
        int o = i >> 4, kg = i & 15;
        *(uint4*)&sW[o][kg * 8] = *(const uint4*)&W[(size_t)(o0 + o) * Cc + kg * 8];
    }
    if (xin) {
        const float* Xb = xin + (size_t)b * Cc * Lc;
        for (int i = tid; i < 128 * 8; i += 256) {
            int c = i >> 3, lg = i & 7;
            float scl = gnscl[b * Cc + c];
            float shf = gnshf[b * Cc + c];
            const float* src = &Xb[(size_t)c * Lc + l0 + lg * 8];
            float4 v0 = *(const float4*)src;
            float4 v1 = *(const float4*)(src + 4);
            uint4 w;
            w.x = cvtb2(v0.y * scl + shf, v0.x * scl + shf);
            w.y = cvtb2(v0.w * scl + shf, v0.z * scl + shf);
            w.z = cvtb2(v1.y * scl + shf, v1.x * scl + shf);
            w.w = cvtb2(v1.w * scl + shf, v1.z * scl + shf);
            *(uint4*)&sA[c][lg * 8] = w;
        }
    } else {
        const bf16* Ab = A + (size_t)b * Cc * Lc;
        for (int i = tid; i < 128 * 8; i += 256) {
            int c = i >> 3, lg = i & 7;
            *(uint4*)&sA[c][lg * 8] = *(const uint4*)&Ab[(size_t)c * Lc + l0 + lg * 8];
        }
    }
    __syncthreads();

    int m0w = (warp >> 2) * 32;
    int n0w = (warp & 3) * 16;
    int g8 = (lane >> 3) & 1;
    int g16 = lane >> 4;
    int r7 = lane & 7;
    int l15 = lane & 15;

    float acc[2][2][4] = {};

#pragma unroll
    for (int kt = 0; kt < 8; kt++) {
        unsigned a0[4], a1[4], bb[4];
        ldsm_x4(a0[0], a0[1], a0[2], a0[3], &sW[m0w + l15][kt * 16 + g16 * 8]);
        ldsm_x4(a1[0], a1[1], a1[2], a1[3], &sW[m0w + 16 + l15][kt * 16 + g16 * 8]);
        ldsm_x4_t(bb[0], bb[1], bb[2], bb[3], &sA[kt * 16 + g8 * 8 + r7][n0w + g16 * 8]);
        mma16816(acc[0][0], a0, bb[0], bb[1]);
        mma16816(acc[0][1], a0, bb[2], bb[3]);
        mma16816(acc[1][0], a1, bb[0], bb[1]);
        mma16816(acc[1][1], a1, bb[2], bb[3]);
    }

    int grp = lane >> 2, tig = lane & 3;
#pragma unroll
    for (int mt = 0; mt < 2; mt++) {
#pragma unroll
        for (int nt = 0; nt < 2; nt++) {
            int o = o0 + m0w + 16 * mt + grp;
            int l = l0 + n0w + 8 * nt + 2 * tig;
            size_t idx = ((size_t)b * M + o) * Lc + l;
            float* d = acc[mt][nt];
            if (outb) {
                *(unsigned*)&outb[idx] = pack_bf16(d[0], d[1]);
                *(unsigned*)&outb[idx + (size_t)8 * Lc] = pack_bf16(d[2], d[3]);
            } else {
                float bv0 = bias[o], bv1 = bias[o + 8];
                outf[idx]     = d[0] + bv0 + resid[idx];
                outf[idx + 1] = d[1] + bv0 + resid[idx + 1];
                outf[idx + (size_t)8 * Lc]     = d[2] + bv1 + resid[idx + (size_t)8 * Lc];
                outf[idx + (size_t)8 * Lc + 1] = d[3] + bv1 + resid[idx + (size_t)8 * Lc + 1];
            }
        }
    }
}

// ---------------------------------------------------------------------------
// Flash attention, mma.sync bf16, no max-tracking. 128-thread CTAs (4/SM):
// 4 independent barrier domains per SM so one CTA's exp/cvt phase overlaps
// another CTA's MMA phase. TQ=128: 4 warps, each owns two 16-row q-subtiles
// (rows warp*16+sub*64) sharing K/V fragments. Packed bf16x2 ex2 -> P;
// row sums via P x ones MMA. 4-deep cp.async pipeline, one sync per tile.
// ---------------------------------------------------------------------------
#define TQ 128
#define TSs 64
#define KSTR 72
#define QSTR 136
#define NBUF 4
#define ONESBF 0x3F803F80u

__global__ __launch_bounds__(128, 4) void attn_mma_kernel(
    const bf16* __restrict__ qkv,
    bf16* __restrict__ o_out)
{
    __shared__ __align__(16) bf16 sQ[32][QSTR];          // 8.7 KB (also out staging)
    __shared__ __align__(16) bf16 sK[NBUF][32][KSTR];    // 18.4 KB
    __shared__ __align__(16) bf16 sV[NBUF][32][KSTR];    // 18.4 KB

    int bh = blockIdx.y;
    int b = bh >> 2;
    int h = bh & 3;
    int t0 = blockIdx.x * TQ;

    const bf16* Qp = qkv + ((size_t)b * 384 + h * 96) * Lc;
    const bf16* Kp = Qp + (size_t)32 * Lc;
    const bf16* Vp = Qp + (size_t)64 * Lc;

    int tid = threadIdx.x;
    int lane = tid & 31;
    int warp = tid >> 5;

    // copy layout: 128 threads, K/V tile = 32c x 64s bf16 = 4 KB each.
    // Each thread: 2 cp16 per matrix (s and s+32).
    const int c_cp = tid >> 2;            // 0..31
    const int s_cp = (tid & 3) * 8;       // 0,8,16,24

    // Q tile [c][t], 128 wide: 512 uint4 over 128 threads
    for (int i = tid; i < 32 * 16; i += 128) {
        int c = i >> 4, tg = i & 15;
        *(uint4*)&sQ[c][tg * 8] = *(const uint4*)&Qp[(size_t)c * Lc + t0 + tg * 8];
    }

    // Prefetch tiles 0,1,2
#pragma unroll
    for (int p = 0; p < 3; p++) {
        cp16(&sK[p][c_cp][s_cp],      &Kp[(size_t)c_cp * Lc + p * TSs + s_cp]);
        cp16(&sK[p][c_cp][s_cp + 32], &Kp[(size_t)c_cp * Lc + p * TSs + s_cp + 32]);
        cp16(&sV[p][c_cp][s_cp],      &Vp[(size_t)c_cp * Lc + p * TSs + s_cp]);
        cp16(&sV[p][c_cp][s_cp + 32], &Vp[(size_t)c_cp * Lc + p * TSs + s_cp + 32]);
        CP_COMMIT();
    }
    __syncthreads();  // sQ visible

    const int g8  = (lane >> 3) & 1;
    const int g16 = lane >> 4;
    const int r7  = lane & 7;

    // Q A-fragments for both subtiles (hoisted)
    unsigned qf[2][2][4];  // [sub][kk][4]
#pragma unroll
    for (int sub = 0; sub < 2; sub++) {
        int tw = warp * 16 + sub * 64;
#pragma unroll
        for (int kk = 0; kk < 2; kk++) {
            int c = 16 * kk + g16 * 8 + r7;
            ldsm_x4_t(qf[sub][kk][0], qf[sub][kk][1], qf[sub][kk][2], qf[sub][kk][3],
                      &sQ[c][tw + g8 * 8]);
        }
    }

    float o0[4][4] = {}, o1[4][4] = {};
    float ls0[4] = {}, ls1[4] = {};

    const int NT = Lc / TSs;  // 64
#pragma unroll 4
    for (int it = 0; it < NT; it++) {
        CP_WAIT(2);        // tile it landed
        __syncthreads();   // all threads' tile it visible; compute it-1 done

        if (it + 3 < NT) {
            int s0n = (it + 3) * TSs;
            int nb = (it + 3) & (NBUF - 1);
            cp16(&sK[nb][c_cp][s_cp],      &Kp[(size_t)c_cp * Lc + s0n + s_cp]);
            cp16(&sK[nb][c_cp][s_cp + 32], &Kp[(size_t)c_cp * Lc + s0n + s_cp + 32]);
            cp16(&sV[nb][c_cp][s_cp],      &Vp[(size_t)c_cp * Lc + s0n + s_cp]);
            cp16(&sV[nb][c_cp][s_cp + 32], &Vp[(size_t)c_cp * Lc + s0n + s_cp + 32]);
        }
        CP_COMMIT();

        const int buf = it & (NBUF - 1);

        // two 32-wide halves per tile; K/V fragments shared by both subtiles
#pragma unroll
        for (int hh = 0; hh < 2; hh++) {
            // ---- S = Q K^T for (2x16) x 32 (log2 domain) ----
            float sa[4][4], sb[4][4];
#pragma unroll
            for (int j = 0; j < 4; j++)
#pragma unroll
                for (int r = 0; r < 4; r++) { sa[j][r] = 0.f; sb[j][r] = 0.f; }

#pragma unroll
            for (int kk = 0; kk < 2; kk++) {
                int c = 16 * kk + g8 * 8 + r7;
#pragma unroll
                for (int jp = 0; jp < 2; jp++) {
                    unsigned b0, b1, b2, b3;
                    ldsm_x4_t(b0, b1, b2, b3, &sK[buf][c][16 * (2 * hh + jp) + g16 * 8]);
                    mma16816(sa[2 * jp],     qf[0][kk], b0, b1);
                    mma16816(sa[2 * jp + 1], qf[0][kk], b2, b3);
                    mma16816(sb[2 * jp],     qf[1][kk], b0, b1);
                    mma16816(sb[2 * jp + 1], qf[1][kk], b2, b3);
                }
            }

            // ---- P = 2^S (packed bf16x2); O += P V ; ls += P x ones ----
#pragma unroll
            for (int h2 = 0; h2 < 2; h2++) {
                int j = 2 * h2;
                unsigned pf0[4], pf1[4];
                pf0[0] = ex2b2(cvtb2(sa[j][1],     sa[j][0]));
                pf0[1] = ex2b2(cvtb2(sa[j][3],     sa[j][2]));
                pf0[2] = ex2b2(cvtb2(sa[j + 1][1], sa[j + 1][0]));
                pf0[3] = ex2b2(cvtb2(sa[j + 1][3], sa[j + 1][2]));
                pf1[0] = ex2b2(cvtb2(sb[j][1],     sb[j][0]));
                pf1[1] = ex2b2(cvtb2(sb[j][3],     sb[j][2]));
                pf1[2] = ex2b2(cvtb2(sb[j + 1][1], sb[j + 1][0]));
                pf1[3] = ex2b2(cvtb2(sb[j + 1][3], sb[j + 1][2]));
                mma16816(ls0, pf0, ONESBF, ONESBF);
                mma16816(ls1, pf1, ONESBF, ONESBF);
                int kcol = 16 * (2 * hh + h2) + g8 * 8;
#pragma unroll
                for (int nbp = 0; nbp < 2; nbp++) {
                    int c = 16 * nbp + g16 * 8 + r7;
                    unsigned b0, b1, b2, b3;
                    ldsm_x4(b0, b1, b2, b3, &sV[buf][c][kcol]);
                    mma16816(o0[2 * nbp],     pf0, b0, b1);
                    mma16816(o0[2 * nbp + 1], pf0, b2, b3);
                    mma16816(o1[2 * nbp],     pf1, b0, b1);
                    mma16816(o1[2 * nbp + 1], pf1, b2, b3);
                }
            }
        }
    }

    // ---- finalize both subtiles: normalize, stage, coalesced store ----
    int grp = lane >> 2;
    int tig = lane & 3;
    {
        float invA = 1.f / ls0[0];
        float invB = 1.f / ls0[2];
        int tw = warp * 16;
#pragma unroll
        for (int nb = 0; nb < 4; nb++) {
            int c = 8 * nb + 2 * tig;
            sQ[c][tw + grp]         = __float2bfloat16_rn(o0[nb][0] * invA);
            sQ[c + 1][tw + grp]     = __float2bfloat16_rn(o0[nb][1] * invA);
            sQ[c][tw + 8 + grp]     = __float2bfloat16_rn(o0[nb][2] * invB);
            sQ[c + 1][tw + 8 + grp] = __float2bfloat16_rn(o0[nb][3] * invB);
        }
    }
    {
        float invA = 1.f / ls1[0];
        float invB = 1.f / ls1[2];
        int tw = warp * 16 + 64;
#pragma unroll
        for (int nb = 0; nb < 4; nb++) {
            int c = 8 * nb + 2 * tig;
            sQ[c][tw + grp]         = __float2bfloat16_rn(o1[nb][0] * invA);
            sQ[c + 1][tw + grp]     = __float2bfloat16_rn(o1[nb][1] * invA);
            sQ[c][tw + 8 + grp]     = __float2bfloat16_rn(o1[nb][2] * invB);
            sQ[c + 1][tw + 8 + grp] = __float2bfloat16_rn(o1[nb][3] * invB);
        }
    }
    __syncthreads();

    bf16* ob = o_out + ((size_t)(b * Cc + h * 32)) * Lc + t0;
    for (int i = tid; i < 32 * 16; i += 128) {
        int c = i >> 4, tg = i & 15;
        *(uint4*)&ob[(size_t)c * Lc + tg * 8] = *(uint4*)&sQ[c][tg * 8];
    }
}

// ---------------------------------------------------------------------------
extern "C" void kernel_launch(void* const* d_in, const int* in_sizes, int n_in,
                              void* d_out, int out_size)
{
    const float* x      = (const float*)d_in[0];
    const float* w_qkv  = (const float*)d_in[1];
    const float* w_proj = (const float*)d_in[2];
    const float* b_proj = (const float*)d_in[3];
    const float* gamma  = (const float*)d_in[4];
    const float* beta   = (const float*)d_in[5];
    float* out = (float*)d_out;

    bf16 *qkvb, *oattb, *wqb, *wpb;
    float *gnscl, *gnshf;
    cudaGetSymbolAddress((void**)&qkvb, g_qkvb);
    cudaGetSymbolAddress((void**)&oattb, g_oattb);
    cudaGetSymbolAddress((void**)&wqb, g_wqb);
    cudaGetSymbolAddress((void**)&wpb, g_wpb);
    cudaGetSymbolAddress((void**)&gnscl, g_gnscl);
    cudaGetSymbolAddress((void**)&gnshf, g_gnshf);

    // 0. Weight conversion
    prep_w_kernel<<<64, 256>>>(w_qkv, w_proj, wqb, wpb);

    // 1. GroupNorm stats only (normalization fused into QKV GEMM)
    gn_stats_kernel<<<Bc * 32, 256>>>(x, gamma, beta, gnscl, gnshf);

    // 2. QKV projection (bf16 mma) with fused GN on A-load
    gemm_mma_kernel<<<dim3(Lc / 64, 384 / 64, Bc), 256>>>(
        wqb, nullptr, x, gnscl, gnshf, qkvb, nullptr, nullptr, nullptr, 384);

    // 3. Attention (TQ=128, 128-thread CTAs, 4/SM)
    attn_mma_kernel<<<dim3(Lc / TQ, Bc * Hh), 128>>>(qkvb, oattb);

    // 4. Output projection + bias + residual
    gemm_mma_kernel<<<dim3(Lc / 64, Cc / 64, Bc), 256>>>(
        wpb, oattb, nullptr, nullptr, nullptr, nullptr, out, b_proj, x, Cc);
}

// round 17
// speedup vs baseline: 1.0512x; 1.0512x over previous
#include <cuda_runtime.h>
#include <cuda_bf16.h>
#include <math.h>

#define Bc 4
#define Cc 128
#define Lc 4096
#define Hh 4

typedef __nv_bfloat16 bf16;

// qscale = hd^-1/2 * log2(e), folded into W_q rows
#define QSCALE (0.17677669529663687f * 1.4426950408889634f)

// Scratch (allocation-free __device__ globals, 16B-aligned)
__device__ __align__(16) bf16 g_qkvb[Bc * 3 * Cc * Lc];  // qkv bf16      (12.6 MB)
__device__ __align__(16) bf16 g_oattb[Bc * Cc * Lc];     // attn out      (4 MB)
__device__ __align__(16) bf16 g_wqb[3 * Cc * Cc];
__device__ __align__(16) bf16 g_wpb[Cc * Cc];
__device__ __align__(16) float g_gnscl[Bc * Cc];         // per (b,c) scale
__device__ __align__(16) float g_gnshf[Bc * Cc];         // per (b,c) shift

// ---------------------------------------------------------------------------
// helpers
// ---------------------------------------------------------------------------
__device__ __forceinline__ void ldsm_x4_t(unsigned& r0, unsigned& r1, unsigned& r2, unsigned& r3, const void* p) {
    unsigned addr = (unsigned)__cvta_generic_to_shared(p);
    asm volatile("ldmatrix.sync.aligned.m8n8.x4.trans.shared.b16 {%0,%1,%2,%3}, [%4];"
                 : "=r"(r0), "=r"(r1), "=r"(r2), "=r"(r3) : "r"(addr));
}
__device__ __forceinline__ void ldsm_x4(unsigned& r0, unsigned& r1, unsigned& r2, unsigned& r3, const void* p) {
    unsigned addr = (unsigned)__cvta_generic_to_shared(p);
    asm volatile("ldmatrix.sync.aligned.m8n8.x4.shared.b16 {%0,%1,%2,%3}, [%4];"
                 : "=r"(r0), "=r"(r1), "=r"(r2), "=r"(r3) : "r"(addr));
}
__device__ __forceinline__ void mma16816(float* d, const unsigned* a, unsigned b0, unsigned b1) {
    asm volatile(
        "mma.sync.aligned.m16n8k16.row.col.f32.bf16.bf16.f32 "
        "{%0,%1,%2,%3},{%4,%5,%6,%7},{%8,%9},{%0,%1,%2,%3};"
        : "+f"(d[0]), "+f"(d[1]), "+f"(d[2]), "+f"(d[3])
        : "r"(a[0]), "r"(a[1]), "r"(a[2]), "r"(a[3]), "r"(b0), "r"(b1));
}
__device__ __forceinline__ unsigned pack_bf16(float lo, float hi) {
    __nv_bfloat162 h = __float22bfloat162_rn(make_float2(lo, hi));
    return *reinterpret_cast<unsigned*>(&h);
}
// {hi, lo} fp32 -> bf16x2 (lo in low half)
__device__ __forceinline__ unsigned cvtb2(float hi, float lo) {
    unsigned r;
    asm("cvt.rn.bf16x2.f32 %0, %1, %2;" : "=r"(r) : "f"(hi), "f"(lo));
    return r;
}
// packed bf16x2 2^x
__device__ __forceinline__ unsigned ex2b2(unsigned x) {
    unsigned r;
    asm("ex2.approx.ftz.bf16x2 %0, %1;" : "=r"(r) : "r"(x));
    return r;
}
__device__ __forceinline__ void cp16(void* smem, const void* gmem) {
    unsigned s = (unsigned)__cvta_generic_to_shared(smem);
    asm volatile("cp.async.cg.shared.global [%0], [%1], 16;" :: "r"(s), "l"(gmem));
}
#define CP_COMMIT() asm volatile("cp.async.commit_group;")
#define CP_WAIT(N)  asm volatile("cp.async.wait_group %0;" :: "n"(N))

// ---------------------------------------------------------------------------
// Fused prep: blocks [0,128) = GroupNorm stats; blocks [128,192) = weight conv.
// ---------------------------------------------------------------------------
__global__ __launch_bounds__(256) void prep_kernel(
    const float* __restrict__ x,
    const float* __restrict__ gamma,
    const float* __restrict__ beta,
    const float* __restrict__ wq, const float* __restrict__ wp,
    float* __restrict__ gnscl, float* __restrict__ gnshf,
    bf16* __restrict__ wqb, bf16* __restrict__ wpb)
{
    if (blockIdx.x < 128) {
        // ---- GroupNorm stats: one block per (b, group) ----
        const int GS = 4 * Lc;  // 16384
        int bg = blockIdx.x;
        size_t base = (size_t)bg * GS;

        float s = 0.f, s2 = 0.f;
        for (int i = threadIdx.x; i < GS; i += 256) {
            float v = x[base + i];
            s += v;
            s2 += v * v;
        }
        __shared__ float rs[256], rs2[256];
        rs[threadIdx.x] = s;
        rs2[threadIdx.x] = s2;
        __syncthreads();
        for (int st = 128; st > 0; st >>= 1) {
            if (threadIdx.x < st) {
                rs[threadIdx.x] += rs[threadIdx.x + st];
                rs2[threadIdx.x] += rs2[threadIdx.x + st];
            }
            __syncthreads();
        }
        if (threadIdx.x < 4) {
            float mu = rs[0] * (1.f / GS);
            float var = rs2[0] * (1.f / GS) - mu * mu;
            float rinv = rsqrtf(var + 1e-5f);
            int b = bg >> 5;
            int c = (bg & 31) * 4 + threadIdx.x;
            float scl = rinv * gamma[c];
            gnscl[b * Cc + c] = scl;
            gnshf[b * Cc + c] = beta[c] - mu * scl;
        }
    } else {
        // ---- weight conversion ----
        int i = (blockIdx.x - 128) * 256 + threadIdx.x;
        int NTH = 64 * 256;
        for (int e = i; e < 3 * Cc * Cc; e += NTH) {
            int row = e >> 7;
            float s = ((row % 96) < 32) ? QSCALE : 1.f;
            wqb[e] = __float2bfloat16_rn(wq[e] * s);
        }
        for (int e = i; e < Cc * Cc; e += NTH)
            wpb[e] = __float2bfloat16_rn(wp[e]);
    }
}

// ---------------------------------------------------------------------------
// bf16 MMA GEMM: Out[b][o][l] = sum_c W[o][c] * A[b][c][l]
// Block tile 128o x 64l x 128c. 8 warps = 4m x 2n, warp tile 32o x 32l.
// If xin != null: fused GroupNorm on the A-load path.
// ---------------------------------------------------------------------------
__global__ __launch_bounds__(256) void gemm_mma_kernel(
    const bf16* __restrict__ W,
    const bf16* __restrict__ A,
    const float* __restrict__ xin,
    const float* __restrict__ gnscl,
    const float* __restrict__ gnshf,
    bf16* __restrict__ outb,
    float* __restrict__ outf,
    const float* __restrict__ bias,
    const float* __restrict__ resid,
    int M)
{
    __shared__ __align__(16) bf16 sW[128][136];   // 34.8 KB
    __shared__ __align__(16) bf16 sA[128][72];    // 18.4 KB

    int b = blockIdx.z;
    int o0 = blockIdx.y * 128;
    int l0 = blockIdx.x * 64;
    int tid = threadIdx.x;
    int lane = tid & 31;
    int warp = tid >> 5;

    // W tile: 128 rows x 128 cols = 2048 uint4
    for (int i = tid; i < 128 * 16; i += 256) {
        int o = i >> 4, kg = i & 15;
        *(uint4*)&sW[o][kg * 8] = *(const uint4*)&W[(size_t)(o0 + o) * Cc + kg * 8];
    }
    if (xin) {
        const float* Xb = xin + (size_t)b * Cc * Lc;
        for (int i = tid; i < 128 * 8; i += 256) {
            int c = i >> 3, lg = i & 7;
            float scl = gnscl[b * Cc + c];
            float shf = gnshf[b * Cc + c];
            const float* src = &Xb[(size_t)c * Lc + l0 + lg * 8];
            float4 v0 = *(const float4*)src;
            float4 v1 = *(const float4*)(src + 4);
            uint4 w;
            w.x = cvtb2(v0.y * scl + shf, v0.x * scl + shf);
            w.y = cvtb2(v0.w * scl + shf, v0.z * scl + shf);
            w.z = cvtb2(v1.y * scl + shf, v1.x * scl + shf);
            w.w = cvtb2(v1.w * scl + shf, v1.z * scl + shf);
            *(uint4*)&sA[c][lg * 8] = w;
        }
    } else {
        const bf16* Ab = A + (size_t)b * Cc * Lc;
        for (int i = tid; i < 128 * 8; i += 256) {
            int c = i >> 3, lg = i & 7;
            *(uint4*)&sA[c][lg * 8] = *(const uint4*)&Ab[(size_t)c * Lc + l0 + lg * 8];
        }
    }
    __syncthreads();

    int m0w = (warp >> 1) * 32;
    int n0w = (warp & 1) * 32;
    int g8 = (lane >> 3) & 1;
    int g16 = lane >> 4;
    int r7 = lane & 7;
    int l15 = lane & 15;

    float acc[2][4][4] = {};

#pragma unroll
    for (int kt = 0; kt < 8; kt++) {
        unsigned a0[4], a1[4], bb0[4], bb1[4];
        ldsm_x4(a0[0], a0[1], a0[2], a0[3], &sW[m0w + l15][kt * 16 + g16 * 8]);
        ldsm_x4(a1[0], a1[1], a1[2], a1[3], &sW[m0w + 16 + l15][kt * 16 + g16 * 8]);
        ldsm_x4_t(bb0[0], bb0[1], bb0[2], bb0[3], &sA[kt * 16 + g8 * 8 + r7][n0w + g16 * 8]);
        ldsm_x4_t(bb1[0], bb1[1], bb1[2], bb1[3], &sA[kt * 16 + g8 * 8 + r7][n0w + 16 + g16 * 8]);
        mma16816(acc[0][0], a0, bb0[0], bb0[1]);
        mma16816(acc[0][1], a0, bb0[2], bb0[3]);
        mma16816(acc[0][2], a0, bb1[0], bb1[1]);
        mma16816(acc[0][3], a0, bb1[2], bb1[3]);
        mma16816(acc[1][0], a1, bb0[0], bb0[1]);
        mma16816(acc[1][1], a1, bb0[2], bb0[3]);
        mma16816(acc[1][2], a1, bb1[0], bb1[1]);
        mma16816(acc[1][3], a1, bb1[2], bb1[3]);
    }

    int grp = lane >> 2, tig = lane & 3;
#pragma unroll
    for (int mt = 0; mt < 2; mt++) {
#pragma unroll
        for (int nt = 0; nt < 4; nt++) {
            int o = o0 + m0w + 16 * mt + grp;
            int l = l0 + n0w + 8 * nt + 2 * tig;
            size_t idx = ((size_t)b * M + o) * Lc + l;
            float* d = acc[mt][nt];
            if (outb) {
                *(unsigned*)&outb[idx] = pack_bf16(d[0], d[1]);
                *(unsigned*)&outb[idx + (size_t)8 * Lc] = pack_bf16(d[2], d[3]);
            } else {
                float bv0 = bias[o], bv1 = bias[o + 8];
                outf[idx]     = d[0] + bv0 + resid[idx];
                outf[idx + 1] = d[1] + bv0 + resid[idx + 1];
                outf[idx + (size_t)8 * Lc]     = d[2] + bv1 + resid[idx + (size_t)8 * Lc];
                outf[idx + (size_t)8 * Lc + 1] = d[3] + bv1 + resid[idx + (size_t)8 * Lc + 1];
            }
        }
    }
}

// ---------------------------------------------------------------------------
// Flash attention, mma.sync bf16, no max-tracking. TQ=256: each warp owns two
// 16-row q-subtiles sharing K/V fragments. Grid 256 CTAs, 2 CTAs/SM.
// Packed bf16x2 ex2 -> P fragments; row sums via P x ones MMA.
// 4-deep cp.async pipeline, one sync per tile. (= R12/R15, best variant)
// ---------------------------------------------------------------------------
#define TQ 256
#define TSs 64
#define KSTR 72
#define QSTR 264
#define NBUF 4
#define ONESBF 0x3F803F80u

__global__ __launch_bounds__(256, 2) void attn_mma_kernel(
    const bf16* __restrict__ qkv,
    bf16* __restrict__ o_out)
{
    __shared__ __align__(16) bf16 sQ[32][QSTR];          // 16.9 KB (also out staging)
    __shared__ __align__(16) bf16 sK[NBUF][32][KSTR];    // 18.4 KB
    __shared__ __align__(16) bf16 sV[NBUF][32][KSTR];    // 18.4 KB

    int bh = blockIdx.y;
    int b = bh >> 2;
    int h = bh & 3;
    int t0 = blockIdx.x * TQ;

    const bf16* Qp = qkv + ((size_t)b * 384 + h * 96) * Lc;
    const bf16* Kp = Qp + (size_t)32 * Lc;
    const bf16* Vp = Qp + (size_t)64 * Lc;

    int tid = threadIdx.x;
    int lane = tid & 31;
    int warp = tid >> 5;

    const int c_cp = tid >> 3;      // 0..31
    const int s_cp = (tid & 7) * 8; // 0..56

    // Q tile [c][t], 256 wide (pre-scaled via W_q rows): 1024 uint4
    for (int i = tid; i < 32 * 32; i += 256) {
        int c = i >> 5, tg = i & 31;
        *(uint4*)&sQ[c][tg * 8] = *(const uint4*)&Qp[(size_t)c * Lc + t0 + tg * 8];
    }

    // Prefetch tiles 0,1,2
#pragma unroll
    for (int p = 0; p < 3; p++) {
        cp16(&sK[p][c_cp][s_cp], &Kp[(size_t)c_cp * Lc + p * TSs + s_cp]);
        cp16(&sV[p][c_cp][s_cp], &Vp[(size_t)c_cp * Lc + p * TSs + s_cp]);
        CP_COMMIT();
    }
    __syncthreads();  // sQ visible

    const int g8  = (lane >> 3) & 1;
    const int g16 = lane >> 4;
    const int r7  = lane & 7;

    // Q A-fragments for both subtiles (hoisted)
    unsigned qf[2][2][4];  // [sub][kk][4]
#pragma unroll
    for (int sub = 0; sub < 2; sub++) {
        int tw = warp * 16 + sub * 128;
#pragma unroll
        for (int kk = 0; kk < 2; kk++) {
            int c = 16 * kk + g16 * 8 + r7;
            ldsm_x4_t(qf[sub][kk][0], qf[sub][kk][1], qf[sub][kk][2], qf[sub][kk][3],
                      &sQ[c][tw + g8 * 8]);
        }
    }

    float o0[4][4] = {}, o1[4][4] = {};
    float ls0[4] = {}, ls1[4] = {};

    const int NT = Lc / TSs;  // 64
#pragma unroll 4
    for (int it = 0; it < NT; it++) {
        CP_WAIT(2);        // tile it landed
        __syncthreads();   // all threads' tile it visible; compute it-1 done

        if (it + 3 < NT) {
            int s0n = (it + 3) * TSs;
            int nb = (it + 3) & (NBUF - 1);
            cp16(&sK[nb][c_cp][s_cp], &Kp[(size_t)c_cp * Lc + s0n + s_cp]);
            cp16(&sV[nb][c_cp][s_cp], &Vp[(size_t)c_cp * Lc + s0n + s_cp]);
        }
        CP_COMMIT();

        const int buf = it & (NBUF - 1);

        // two 32-wide halves per tile; K/V fragments shared by both subtiles
#pragma unroll
        for (int hh = 0; hh < 2; hh++) {
            // ---- S = Q K^T for (2x16) x 32 (log2 domain) ----
            float sa[4][4], sb[4][4];
#pragma unroll
            for (int j = 0; j < 4; j++)
#pragma unroll
                for (int r = 0; r < 4; r++) { sa[j][r] = 0.f; sb[j][r] = 0.f; }

#pragma unroll
            for (int kk = 0; kk < 2; kk++) {
                int c = 16 * kk + g8 * 8 + r7;
#pragma unroll
                for (int jp = 0; jp < 2; jp++) {
                    unsigned b0, b1, b2, b3;
                    ldsm_x4_t(b0, b1, b2, b3, &sK[buf][c][16 * (2 * hh + jp) + g16 * 8]);
                    mma16816(sa[2 * jp],     qf[0][kk], b0, b1);
                    mma16816(sa[2 * jp + 1], qf[0][kk], b2, b3);
                    mma16816(sb[2 * jp],     qf[1][kk], b0, b1);
                    mma16816(sb[2 * jp + 1], qf[1][kk], b2, b3);
                }
            }

            // ---- P = 2^S (packed bf16x2); O += P V ; ls += P x ones ----
#pragma unroll
            for (int h2 = 0; h2 < 2; h2++) {
                int j = 2 * h2;
                unsigned pf0[4], pf1[4];
                pf0[0] = ex2b2(cvtb2(sa[j][1],     sa[j][0]));
                pf0[1] = ex2b2(cvtb2(sa[j][3],     sa[j][2]));
                pf0[2] = ex2b2(cvtb2(sa[j + 1][1], sa[j + 1][0]));
                pf0[3] = ex2b2(cvtb2(sa[j + 1][3], sa[j + 1][2]));
                pf1[0] = ex2b2(cvtb2(sb[j][1],     sb[j][0]));
                pf1[1] = ex2b2(cvtb2(sb[j][3],     sb[j][2]));
                pf1[2] = ex2b2(cvtb2(sb[j + 1][1], sb[j + 1][0]));
                pf1[3] = ex2b2(cvtb2(sb[j + 1][3], sb[j + 1][2]));
                mma16816(ls0, pf0, ONESBF, ONESBF);
                mma16816(ls1, pf1, ONESBF, ONESBF);
                int kcol = 16 * (2 * hh + h2) + g8 * 8;
#pragma unroll
                for (int nbp = 0; nbp < 2; nbp++) {
                    int c = 16 * nbp + g16 * 8 + r7;
                    unsigned b0, b1, b2, b3;
                    ldsm_x4(b0, b1, b2, b3, &sV[buf][c][kcol]);
                    mma16816(o0[2 * nbp],     pf0, b0, b1);
                    mma16816(o0[2 * nbp + 1], pf0, b2, b3);
                    mma16816(o1[2 * nbp],     pf1, b0, b1);
                    mma16816(o1[2 * nbp + 1], pf1, b2, b3);
                }
            }
        }
    }

    // ---- finalize both subtiles: normalize, stage, coalesced store ----
    int grp = lane >> 2;
    int tig = lane & 3;
    {
        float invA = 1.f / ls0[0];
        float invB = 1.f / ls0[2];
        int tw = warp * 16;
#pragma unroll
        for (int nb = 0; nb < 4; nb++) {
            int c = 8 * nb + 2 * tig;
            sQ[c][tw + grp]         = __float2bfloat16_rn(o0[nb][0] * invA);
            sQ[c + 1][tw + grp]     = __float2bfloat16_rn(o0[nb][1] * invA);
            sQ[c][tw + 8 + grp]     = __float2bfloat16_rn(o0[nb][2] * invB);
            sQ[c + 1][tw + 8 + grp] = __float2bfloat16_rn(o0[nb][3] * invB);
        }
    }
    {
        float invA = 1.f / ls1[0];
        float invB = 1.f / ls1[2];
        int tw = warp * 16 + 128;
#pragma unroll
        for (int nb = 0; nb < 4; nb++) {
            int c = 8 * nb + 2 * tig;
            sQ[c][tw + grp]         = __float2bfloat16_rn(o1[nb][0] * invA);
            sQ[c + 1][tw + grp]     = __float2bfloat16_rn(o1[nb][1] * invA);
            sQ[c][tw + 8 + grp]     = __float2bfloat16_rn(o1[nb][2] * invB);
            sQ[c + 1][tw + 8 + grp] = __float2bfloat16_rn(o1[nb][3] * invB);
        }
    }
    __syncthreads();

    bf16* ob = o_out + ((size_t)(b * Cc + h * 32)) * Lc + t0;
    for (int i = tid; i < 32 * 32; i += 256) {
        int c = i >> 5, tg = i & 31;
        *(uint4*)&ob[(size_t)c * Lc + tg * 8] = *(uint4*)&sQ[c][tg * 8];
    }
}

// ---------------------------------------------------------------------------
extern "C" void kernel_launch(void* const* d_in, const int* in_sizes, int n_in,
                              void* d_out, int out_size)
{
    const float* x      = (const float*)d_in[0];
    const float* w_qkv  = (const float*)d_in[1];
    const float* w_proj = (const float*)d_in[2];
    const float* b_proj = (const float*)d_in[3];
    const float* gamma  = (const float*)d_in[4];
    const float* beta   = (const float*)d_in[5];
    float* out = (float*)d_out;

    bf16 *qkvb, *oattb, *wqb, *wpb;
    float *gnscl, *gnshf;
    cudaGetSymbolAddress((void**)&qkvb, g_qkvb);
    cudaGetSymbolAddress((void**)&oattb, g_oattb);
    cudaGetSymbolAddress((void**)&wqb, g_wqb);
    cudaGetSymbolAddress((void**)&wpb, g_wpb);
    cudaGetSymbolAddress((void**)&gnscl, g_gnscl);
    cudaGetSymbolAddress((void**)&gnshf, g_gnshf);

    // 0. Fused prep: GN stats + weight conversion in one launch
    prep_kernel<<<192, 256>>>(x, gamma, beta, w_qkv, w_proj,
                              gnscl, gnshf, wqb, wpb);

    // 1. QKV projection (bf16 mma, 128o x 64l tiles) with fused GN on A-load
    gemm_mma_kernel<<<dim3(Lc / 64, 384 / 128, Bc), 256>>>(
        wqb, nullptr, x, gnscl, gnshf, qkvb, nullptr, nullptr, nullptr, 384);

    // 2. Attention (TQ=256)
    attn_mma_kernel<<<dim3(Lc / TQ, Bc * Hh), 256>>>(qkvb, oattb);

    // 3. Output projection (128o x 64l: A read exactly once) + bias + residual
    gemm_mma_kernel<<<dim3(Lc / 64, Cc / 128, Bc), 256>>>(
        wpb, oattb, nullptr, nullptr, nullptr, nullptr, out, b_proj, x, Cc);
}